// round 6
// baseline (speedup 1.0000x reference)
#include <cuda_runtime.h>

// ---------------------------------------------------------------------------
// Image-per-lane + packed f32x2 (FFMA2) edition. 3 kernels:
//  1) transpose  : x[B][256] -> g_xt[256][B]
//  2) conv1      : 2 images/lane packed conv -> g_a1[768][B]
//  3) conv2+FC   : 2 images/lane packed grouped conv, FC1 fused into conv2
//                  epilogue (no staging), FC2 -> out
// All FMAs are fma.rn.f32x2 (2 images per instruction). Weights/biases are
// stored in shared pre-duplicated {w,w} so LDS.64 broadcast = packed operand.
// ---------------------------------------------------------------------------

typedef unsigned long long u64;
#define NEG1P 0xBF800000BF800000ULL   // {-1.0f, -1.0f}

__device__ __forceinline__ u64 ffma2(u64 a, u64 b, u64 c) {
    u64 d;
    asm("fma.rn.f32x2 %0, %1, %2, %3;" : "=l"(d) : "l"(a), "l"(b), "l"(c));
    return d;
}
__device__ __forceinline__ u64 pack2(float lo, float hi) {
    u64 d; asm("mov.b64 %0, {%1, %2};" : "=l"(d) : "f"(lo), "f"(hi)); return d;
}
__device__ __forceinline__ float2 unpack2(u64 v) {
    float2 r; asm("mov.b64 {%0, %1}, %2;" : "=f"(r.x), "=f"(r.y) : "l"(v)); return r;
}
__device__ __forceinline__ float2 relu_unpack(u64 v) {
    float2 r = unpack2(v);
    r.x = fmaxf(r.x, 0.f); r.y = fmaxf(r.y, 0.f);
    return r;
}
__device__ __forceinline__ u64 relu2(u64 v) {
    float2 r = relu_unpack(v);
    return pack2(r.x, r.y);
}

#define MAXB 131072
__device__ float g_xt[256 * MAXB];   // transposed input [pos][img]
__device__ float g_a1[768 * MAXB];   // conv1 activations [pos][img]

// ---------------- transpose ----------------
__global__ void __launch_bounds__(256)
transpose_kernel(const float* __restrict__ x, int B)
{
    __shared__ float t[32][33];
    int img0 = blockIdx.x * 32;
    int pos0 = blockIdx.y * 32;
    int tx = threadIdx.x & 31;
    int ty = threadIdx.x >> 5;
    #pragma unroll
    for (int j = 0; j < 32; j += 8)
        t[ty + j][tx] = x[(size_t)(img0 + ty + j) * 256 + pos0 + tx];
    __syncthreads();
    #pragma unroll
    for (int j = 0; j < 32; j += 8)
        g_xt[(size_t)(pos0 + ty + j) * B + img0 + tx] = t[tx][ty + j];
}

// ---------------- conv1 (packed pairs) ----------------
#define K1_THREADS 128

__global__ void __launch_bounds__(K1_THREADS)
conv1_kernel(const float* __restrict__ H1w, const float* __restrict__ H1b, int B)
{
    __shared__ u64 sw[300];    // {w,w}
    __shared__ u64 sb[768];    // {b,b}
    int tid = threadIdx.x;
    for (int i = tid; i < 300; i += K1_THREADS) { float w = H1w[i]; sw[i] = pack2(w, w); }
    for (int i = tid; i < 768; i += K1_THREADS) { float b = H1b[i]; sb[i] = pack2(b, b); }
    __syncthreads();

    int lane = tid & 31;
    int gw = blockIdx.x * (K1_THREADS / 32) + (tid >> 5);
    int nw = gridDim.x * (K1_THREADS / 32);
    int nblk = B >> 6;                      // 64 images per warp-block

    for (int blk = gw; blk < nblk; blk += nw) {
        int img = (blk << 6) + 2 * lane;    // this lane's image pair
        const float* xi = g_xt + img;
        float* ao = g_a1 + img;

        #pragma unroll 1
        for (int half = 0; half < 2; half++) {       // channels 6*half..+5
            #pragma unroll 1
            for (int oy = 0; oy < 8; oy++) {
                u64 acc[6][8];
                #pragma unroll
                for (int c = 0; c < 6; c++)
                    #pragma unroll
                    for (int ox = 0; ox < 8; ox++)
                        acc[c][ox] = sb[(half * 6 + c) * 64 + oy * 8 + ox];

                #pragma unroll 1
                for (int ky = 0; ky < 5; ky++) {
                    int pr = 2 * oy + ky;           // padded row 0..19
                    u64 row[20];
                    row[0] = row[1] = row[18] = row[19] = NEG1P;
                    if (pr >= 2 && pr <= 17) {
                        const float* p = xi + (size_t)((pr - 2) * 16) * B;
                        #pragma unroll
                        for (int i = 0; i < 16; i++)
                            row[2 + i] = *(const u64*)(p + (size_t)i * B);
                    } else {
                        #pragma unroll
                        for (int i = 0; i < 16; i++) row[2 + i] = NEG1P;
                    }
                    #pragma unroll
                    for (int c = 0; c < 6; c++) {
                        const u64* wp = sw + (half * 6 + c) * 25 + ky * 5;
                        #pragma unroll
                        for (int kx = 0; kx < 5; kx++) {
                            u64 wv = wp[kx];
                            #pragma unroll
                            for (int ox = 0; ox < 8; ox++)
                                acc[c][ox] = ffma2(row[2 * ox + kx], wv, acc[c][ox]);
                        }
                    }
                }
                #pragma unroll
                for (int c = 0; c < 6; c++)
                    #pragma unroll
                    for (int ox = 0; ox < 8; ox++) {
                        float2 v = relu_unpack(acc[c][ox]);
                        *(float2*)(ao + (size_t)((half * 6 + c) * 64 + oy * 8 + ox) * B) = v;
                    }
            }
        }
    }
}

// ---------------- conv2 + fused FC ----------------
#define K2_THREADS 128
// u64 smem offsets
#define W2P 0        // 2400  H2w packed, natural [oc][g][25]
#define B2P 2400     // 192
#define W3P 2592     // 5760  H3w packed [k][30]
#define B3P 8352     // 30
#define WOP 8384     // 300   outw packed [j][10]   (16B aligned)
#define BOP 8684     // 10
#define SM_U64 8696
#define SM_BYTES (SM_U64 * 8)   // 69568 bytes

__global__ void __launch_bounds__(K2_THREADS)
conv2fc_kernel(const float* __restrict__ H2w, const float* __restrict__ H2b,
               const float* __restrict__ H3w, const float* __restrict__ H3b,
               const float* __restrict__ outw, const float* __restrict__ outb,
               float* __restrict__ out, int B)
{
    extern __shared__ u64 sm[];
    int tid = threadIdx.x;
    for (int i = tid; i < 2400; i += K2_THREADS) sm[W2P + i] = pack2(H2w[i], H2w[i]);
    for (int i = tid; i < 192;  i += K2_THREADS) sm[B2P + i] = pack2(H2b[i], H2b[i]);
    for (int i = tid; i < 5760; i += K2_THREADS) sm[W3P + i] = pack2(H3w[i], H3w[i]);
    for (int i = tid; i < 30;   i += K2_THREADS) sm[B3P + i] = pack2(H3b[i], H3b[i]);
    for (int i = tid; i < 300;  i += K2_THREADS) sm[WOP + i] = pack2(outw[i], outw[i]);
    for (int i = tid; i < 10;   i += K2_THREADS) sm[BOP + i] = pack2(outb[i], outb[i]);
    __syncthreads();

    int lane = tid & 31;
    int gw = blockIdx.x * (K2_THREADS / 32) + (tid >> 5);
    int nw = gridDim.x * (K2_THREADS / 32);
    int nblk = B >> 6;

    for (int blk = gw; blk < nblk; blk += nw) {
        int img = (blk << 6) + 2 * lane;
        const float* ai = g_a1 + img;

        u64 fc1[30];
        #pragma unroll
        for (int j = 0; j < 30; j++) fc1[j] = sm[B3P + j];

        #pragma unroll 1
        for (int grp = 0; grp < 3; grp++) {
            #pragma unroll 1
            for (int oy = 0; oy < 4; oy++) {
                u64 acc[16];                          // [o][ox], o = local oc
                #pragma unroll
                for (int t = 0; t < 16; t++)
                    acc[t] = sm[B2P + grp * 64 + (t >> 2) * 16 + oy * 4 + (t & 3)];

                #pragma unroll 1
                for (int icl = 0; icl < 8; icl++) {
                    int c = icl + ((grp == 1) ? 4 : ((grp == 2 && icl >= 4) ? 4 : 0));
                    const float* ci = ai + (size_t)(c * 64) * B;
                    #pragma unroll
                    for (int ky = 0; ky < 5; ky++) {
                        int pr = 2 * oy + ky;        // padded row 0..11
                        u64 row[12];
                        row[0] = row[1] = row[10] = row[11] = NEG1P;
                        if (pr >= 2 && pr <= 9) {
                            const float* p = ci + (size_t)((pr - 2) * 8) * B;
                            #pragma unroll
                            for (int i = 0; i < 8; i++)
                                row[2 + i] = *(const u64*)(p + (size_t)i * B);
                        } else {
                            #pragma unroll
                            for (int i = 0; i < 8; i++) row[2 + i] = NEG1P;
                        }
                        #pragma unroll
                        for (int o = 0; o < 4; o++) {
                            const u64* wp = sm + W2P + ((grp * 4 + o) * 8 + icl) * 25 + ky * 5;
                            #pragma unroll
                            for (int kx = 0; kx < 5; kx++) {
                                u64 wv = wp[kx];
                                #pragma unroll
                                for (int ox = 0; ox < 4; ox++)
                                    acc[o * 4 + ox] = ffma2(row[2 * ox + kx], wv, acc[o * 4 + ox]);
                            }
                        }
                    }
                }

                // ---- fused FC1: relu(conv2 out) scattered into fc1 accumulators ----
                #pragma unroll
                for (int t = 0; t < 16; t++) {
                    u64 a = relu2(acc[t]);
                    int k = grp * 64 + (t >> 2) * 16 + oy * 4 + (t & 3);
                    const ulonglong2* wr = (const ulonglong2*)(sm + W3P + k * 30);
                    #pragma unroll
                    for (int m = 0; m < 15; m++) {
                        ulonglong2 w = wr[m];
                        fc1[2 * m]     = ffma2(a, w.x, fc1[2 * m]);
                        fc1[2 * m + 1] = ffma2(a, w.y, fc1[2 * m + 1]);
                    }
                }
            }
        }

        // ---- FC2 ----
        u64 res[10];
        #pragma unroll
        for (int i = 0; i < 10; i++) res[i] = sm[BOP + i];
        #pragma unroll 1
        for (int j = 0; j < 30; j++) {
            u64 v = relu2(fc1[j]);
            const ulonglong2* wr = (const ulonglong2*)(sm + WOP + j * 10);
            #pragma unroll
            for (int m = 0; m < 5; m++) {
                ulonglong2 w = wr[m];
                res[2 * m]     = ffma2(v, w.x, res[2 * m]);
                res[2 * m + 1] = ffma2(v, w.y, res[2 * m + 1]);
            }
        }

        // store both images' outputs: out[img*10 .. img*10+20)
        float lo[10], hi[10];
        #pragma unroll
        for (int i = 0; i < 10; i++) {
            float2 t = unpack2(res[i]);
            lo[i] = t.x; hi[i] = t.y;
        }
        float4* op = (float4*)(out + (size_t)img * 10);
        op[0] = make_float4(lo[0], lo[1], lo[2], lo[3]);
        op[1] = make_float4(lo[4], lo[5], lo[6], lo[7]);
        op[2] = make_float4(lo[8], lo[9], hi[0], hi[1]);
        op[3] = make_float4(hi[2], hi[3], hi[4], hi[5]);
        op[4] = make_float4(hi[6], hi[7], hi[8], hi[9]);
    }
}

// ---------------- launch ----------------
extern "C" void kernel_launch(void* const* d_in, const int* in_sizes, int n_in,
                              void* d_out, int out_size)
{
    const float* x    = (const float*)d_in[0];
    const float* H1w  = (const float*)d_in[1];
    const float* H1b  = (const float*)d_in[2];
    const float* H2w  = (const float*)d_in[3];
    const float* H2b  = (const float*)d_in[4];
    const float* H3w  = (const float*)d_in[5];
    const float* H3b  = (const float*)d_in[6];
    const float* outw = (const float*)d_in[7];
    const float* outb = (const float*)d_in[8];
    float* out = (float*)d_out;

    int B = in_sizes[0] / 256;

    static bool attr_set = false;
    if (!attr_set) {
        cudaFuncSetAttribute(conv2fc_kernel,
                             cudaFuncAttributeMaxDynamicSharedMemorySize,
                             SM_BYTES);
        attr_set = true;
    }

    dim3 tgrid(B / 32, 8);
    transpose_kernel<<<tgrid, 256>>>(x, B);

    int nblk = B / 64;                         // 64-image warp blocks
    int g1 = (nblk + (K1_THREADS / 32) - 1) / (K1_THREADS / 32);
    if (g1 > 1184) g1 = 1184;
    conv1_kernel<<<g1, K1_THREADS>>>(H1w, H1b, B);

    int g2 = (nblk + (K2_THREADS / 32) - 1) / (K2_THREADS / 32);
    if (g2 > 1184) g2 = 1184;
    conv2fc_kernel<<<g2, K2_THREADS, SM_BYTES>>>(H2w, H2b, H3w, H3b,
                                                 outw, outb, out, B);
}

// round 7
// speedup vs baseline: 1.2869x; 1.2869x over previous
#include <cuda_runtime.h>

// ---------------------------------------------------------------------------
// R7: border-constant folding + conv2 memory reorg + lean FFMA2 in conv2fc.
//  1) transpose : x[B][256] -> g_xt[256][B]
//  2) conv1     : scalar, 1 img/lane, folded borders -> g_a1[768][B]
//  3) conv2+FC  : 2 imgs/lane packed f32x2, rows shared across all 12 oc,
//                 FC1 fused via per-oy smem staging, FC2 -> out
// ---------------------------------------------------------------------------

typedef unsigned long long u64;
#define NEG1P 0xBF800000BF800000ULL   // {-1.0f, -1.0f}

__device__ __forceinline__ u64 ffma2(u64 a, u64 b, u64 c) {
    u64 d;
    asm("fma.rn.f32x2 %0, %1, %2, %3;" : "=l"(d) : "l"(a), "l"(b), "l"(c));
    return d;
}
__device__ __forceinline__ u64 pack2(float lo, float hi) {
    u64 d; asm("mov.b64 %0, {%1, %2};" : "=l"(d) : "f"(lo), "f"(hi)); return d;
}
__device__ __forceinline__ float2 unpack2(u64 v) {
    float2 r; asm("mov.b64 {%0, %1}, %2;" : "=f"(r.x), "=f"(r.y) : "l"(v)); return r;
}
__device__ __forceinline__ u64 relu2(u64 v) {
    float2 r = unpack2(v);
    return pack2(fmaxf(r.x, 0.f), fmaxf(r.y, 0.f));
}

#define MAXB 131072
__device__ float g_xt[256 * MAXB];   // transposed input [pos][img]
__device__ float g_a1[768 * MAXB];   // conv1 activations [pos][img]

// ---------------- transpose ----------------
__global__ void __launch_bounds__(256)
transpose_kernel(const float* __restrict__ x, int B)
{
    __shared__ float t[32][33];
    int img0 = blockIdx.x * 32;
    int pos0 = blockIdx.y * 32;
    int tx = threadIdx.x & 31;
    int ty = threadIdx.x >> 5;
    #pragma unroll
    for (int j = 0; j < 32; j += 8)
        t[ty + j][tx] = x[(size_t)(img0 + ty + j) * 256 + pos0 + tx];
    __syncthreads();
    #pragma unroll
    for (int j = 0; j < 32; j += 8)
        g_xt[(size_t)(pos0 + ty + j) * B + img0 + tx] = t[tx][ty + j];
}

// ---------------- conv1: scalar, border-folded ----------------
#define K1_THREADS 128

__global__ void __launch_bounds__(K1_THREADS)
conv1_kernel(const float* __restrict__ H1w, const float* __restrict__ H1b, int B)
{
    __shared__ float sw[300];
    __shared__ float adj[768];     // bias with column-border terms folded in
    int tid = threadIdx.x;
    for (int i = tid; i < 300; i += K1_THREADS) sw[i] = H1w[i];
    for (int i = tid; i < 768; i += K1_THREADS) {
        int c = i >> 6, rem = i & 63, ox = rem & 7;
        float s = H1b[i];
        if (ox == 0) {          // padded cols 0,1 (kx=0,1) are border for all ky
            #pragma unroll
            for (int ky = 0; ky < 5; ky++)
                s += H1w[c * 25 + ky * 5 + 0] + H1w[c * 25 + ky * 5 + 1];
            // border value is -1: contribution = -w  -> subtract
            s -= 2.0f * 0.0f;   // (kept explicit below)
        }
        // redo cleanly: subtract w for each column-oob (ky,kx)
        s = H1b[i];
        if (ox == 0) {
            #pragma unroll
            for (int ky = 0; ky < 5; ky++)
                s -= H1w[c * 25 + ky * 5 + 0] + H1w[c * 25 + ky * 5 + 1];
        }
        if (ox == 7) {
            #pragma unroll
            for (int ky = 0; ky < 5; ky++)
                s -= H1w[c * 25 + ky * 5 + 4];
        }
        adj[i] = s;
    }
    __syncthreads();

    int lane = tid & 31;
    int gw = blockIdx.x * (K1_THREADS / 32) + (tid >> 5);
    int nw = gridDim.x * (K1_THREADS / 32);
    int nblk = B >> 5;

    for (int blk = gw; blk < nblk; blk += nw) {
        int img = (blk << 5) + lane;
        const float* xi = g_xt + img;
        float* ao = g_a1 + img;

        #pragma unroll 1
        for (int oy = 0; oy < 8; oy++) {
            float row[5][16];
            #pragma unroll
            for (int ky = 0; ky < 5; ky++) {
                int r = 2 * oy + ky;                 // padded row 0..19
                if (r >= 2 && r <= 17) {
                    const float* p = xi + (size_t)((r - 2) * 16) * B;
                    #pragma unroll
                    for (int i = 0; i < 16; i++) row[ky][i] = p[(size_t)i * B];
                } else {
                    #pragma unroll
                    for (int i = 0; i < 16; i++) row[ky][i] = -1.f;
                }
            }
            #pragma unroll 1
            for (int c = 0; c < 12; c++) {
                const float* wp = sw + c * 25;
                const float* ap = adj + c * 64 + oy * 8;
                float acc[8];
                #pragma unroll
                for (int ox = 0; ox < 8; ox++) acc[ox] = ap[ox];
                #pragma unroll
                for (int ky = 0; ky < 5; ky++) {
                    #pragma unroll
                    for (int kx = 0; kx < 5; kx++) {
                        float wv = wp[ky * 5 + kx];
                        #pragma unroll
                        for (int ox = 0; ox < 8; ox++) {
                            int col = 2 * ox + kx;          // padded col
                            if (col >= 2 && col <= 17)      // compile-time
                                acc[ox] += row[ky][col - 2] * wv;
                        }
                    }
                }
                float* op = ao + (size_t)(c * 64 + oy * 8) * B;
                #pragma unroll
                for (int ox = 0; ox < 8; ox++)
                    op[(size_t)ox * B] = fmaxf(acc[ox], 0.f);
            }
        }
    }
}

// ---------------- conv2 + fused FC (packed f32x2) ----------------
#define K2_THREADS 128
// u64 smem layout
#define SW2 0        // 2400  H2w packed {w,w}, [oc][g][25]
#define ADJ2 2400    // 192   adjusted bias packed
#define B3P 2592     // 30
#define WOP 2624     // 300   outw packed [j][10]   (byte 20992, 16B aligned)
#define BOP 2924     // 10
#define STG 2944     // 4 warps x 1536 (48 x 32 lanes u64)
#define U64_CNT (2944 + 4 * 1536)          // 9088
#define W3F_OFF U64_CNT                    // float region: 5760 floats
#define SM_BYTES (U64_CNT * 8 + 5760 * 4)  // 95744

__device__ __forceinline__ void conv_block(const u64* __restrict__ wp,
                                           const u64* __restrict__ row,
                                           u64* __restrict__ acc)
{
    #pragma unroll
    for (int kx = 0; kx < 5; kx++) {
        u64 wv = wp[kx];
        #pragma unroll
        for (int ox = 0; ox < 4; ox++) {
            int col = 2 * ox + kx;                 // padded col 0..11
            if (col >= 2 && col <= 9)              // compile-time
                acc[ox] = ffma2(row[col - 2], wv, acc[ox]);
        }
    }
}

__global__ void __launch_bounds__(K2_THREADS)
conv2fc_kernel(const float* __restrict__ H2w, const float* __restrict__ H2b,
               const float* __restrict__ H3w, const float* __restrict__ H3b,
               const float* __restrict__ outw, const float* __restrict__ outb,
               float* __restrict__ out, int B)
{
    extern __shared__ u64 sm[];
    float* w3f = (float*)(sm + W3F_OFF);
    int tid = threadIdx.x;

    for (int i = tid; i < 2400; i += K2_THREADS) sm[SW2 + i] = pack2(H2w[i], H2w[i]);
    for (int i = tid; i < 192; i += K2_THREADS) {
        int oc = i >> 4, rem = i & 15, ox = rem & 3;
        float s = H2b[i];
        if (ox == 0) {
            for (int g = 0; g < 8; g++)
                #pragma unroll
                for (int ky = 0; ky < 5; ky++)
                    s -= H2w[(oc * 8 + g) * 25 + ky * 5 + 0]
                       + H2w[(oc * 8 + g) * 25 + ky * 5 + 1];
        }
        if (ox == 3) {
            for (int g = 0; g < 8; g++)
                #pragma unroll
                for (int ky = 0; ky < 5; ky++)
                    s -= H2w[(oc * 8 + g) * 25 + ky * 5 + 4];
        }
        sm[ADJ2 + i] = pack2(s, s);
    }
    for (int i = tid; i < 30;   i += K2_THREADS) sm[B3P + i] = pack2(H3b[i], H3b[i]);
    for (int i = tid; i < 300;  i += K2_THREADS) sm[WOP + i] = pack2(outw[i], outw[i]);
    for (int i = tid; i < 10;   i += K2_THREADS) sm[BOP + i] = pack2(outb[i], outb[i]);
    for (int i = tid; i < 5760; i += K2_THREADS) w3f[i] = H3w[i];
    __syncthreads();

    int lane = tid & 31;
    int warp = tid >> 5;
    u64* stg = sm + STG + warp * 1536;

    int gw = blockIdx.x * (K2_THREADS / 32) + warp;
    int nw = gridDim.x * (K2_THREADS / 32);
    int nblk = B >> 6;                          // 64-img chunks

    for (int blk = gw; blk < nblk; blk += nw) {
        int img = (blk << 6) + 2 * lane;
        const float* ai = g_a1 + img;

        u64 fc1[30];
        #pragma unroll
        for (int j = 0; j < 30; j++) fc1[j] = sm[B3P + j];

        #pragma unroll 1
        for (int oy = 0; oy < 4; oy++) {
            u64 acc[48];                         // [oc][ox]
            #pragma unroll
            for (int t = 0; t < 48; t++)
                acc[t] = sm[ADJ2 + (t >> 2) * 16 + oy * 4 + (t & 3)];

            #pragma unroll 1
            for (int ic = 0; ic < 12; ic++) {
                #pragma unroll 1
                for (int ky = 0; ky < 5; ky++) {
                    int r = 2 * oy + ky;         // padded row 0..11
                    u64 row[8];
                    if (r >= 2 && r <= 9) {
                        const float* p = ai + (size_t)(ic * 64 + (r - 2) * 8) * B;
                        #pragma unroll
                        for (int i = 0; i < 8; i++)
                            row[i] = *(const u64*)(p + (size_t)i * B);
                    } else {
                        #pragma unroll
                        for (int i = 0; i < 8; i++) row[i] = NEG1P;
                    }
                    int ky5 = ky * 5;
                    if (ic < 8) {                        // grp0: oc 0..3, g=ic
                        int gof = ic * 25 + ky5;
                        #pragma unroll
                        for (int o = 0; o < 4; o++)
                            conv_block(sm + SW2 + (o * 8) * 25 + gof, row, acc + o * 4);
                    }
                    if (ic >= 4) {                       // grp1: oc 4..7, g=ic-4
                        int gof = (ic - 4) * 25 + ky5;
                        #pragma unroll
                        for (int o = 0; o < 4; o++)
                            conv_block(sm + SW2 + ((4 + o) * 8) * 25 + gof, row, acc + (4 + o) * 4);
                    }
                    if (ic < 4 || ic >= 8) {             // grp2: oc 8..11
                        int g = (ic < 4) ? ic : ic - 4;
                        int gof = g * 25 + ky5;
                        #pragma unroll
                        for (int o = 0; o < 4; o++)
                            conv_block(sm + SW2 + ((8 + o) * 8) * 25 + gof, row, acc + (8 + o) * 4);
                    }
                }
            }

            // relu + stage this oy's 48 outputs (own-lane column only)
            #pragma unroll
            for (int t = 0; t < 48; t++)
                stg[t * 32 + lane] = relu2(acc[t]);

            // FC1 partial accumulation (runtime k loop; v from staging)
            #pragma unroll 1
            for (int k = 0; k < 48; k++) {
                u64 v = stg[k * 32 + lane];
                int kk = ((k >> 2) << 4) + (oy << 2) + (k & 3);
                const float* wr = w3f + kk * 30;
                #pragma unroll
                for (int j = 0; j < 15; j++) {
                    float2 wv = *(const float2*)(wr + 2 * j);
                    fc1[2 * j]     = ffma2(v, pack2(wv.x, wv.x), fc1[2 * j]);
                    fc1[2 * j + 1] = ffma2(v, pack2(wv.y, wv.y), fc1[2 * j + 1]);
                }
            }
        }

        // ---- FC2 ----
        u64 res[10];
        #pragma unroll
        for (int i = 0; i < 10; i++) res[i] = sm[BOP + i];
        #pragma unroll
        for (int j = 0; j < 30; j++) {
            u64 v = relu2(fc1[j]);
            const ulonglong2* wr = (const ulonglong2*)(sm + WOP + j * 10);
            #pragma unroll
            for (int m = 0; m < 5; m++) {
                ulonglong2 w = wr[m];
                res[2 * m]     = ffma2(v, w.x, res[2 * m]);
                res[2 * m + 1] = ffma2(v, w.y, res[2 * m + 1]);
            }
        }

        float lo[10], hi[10];
        #pragma unroll
        for (int i = 0; i < 10; i++) {
            float2 t = unpack2(res[i]);
            lo[i] = t.x; hi[i] = t.y;
        }
        float4* op = (float4*)(out + (size_t)img * 10);
        op[0] = make_float4(lo[0], lo[1], lo[2], lo[3]);
        op[1] = make_float4(lo[4], lo[5], lo[6], lo[7]);
        op[2] = make_float4(lo[8], lo[9], hi[0], hi[1]);
        op[3] = make_float4(hi[2], hi[3], hi[4], hi[5]);
        op[4] = make_float4(hi[6], hi[7], hi[8], hi[9]);
    }
}

// ---------------- launch ----------------
extern "C" void kernel_launch(void* const* d_in, const int* in_sizes, int n_in,
                              void* d_out, int out_size)
{
    const float* x    = (const float*)d_in[0];
    const float* H1w  = (const float*)d_in[1];
    const float* H1b  = (const float*)d_in[2];
    const float* H2w  = (const float*)d_in[3];
    const float* H2b  = (const float*)d_in[4];
    const float* H3w  = (const float*)d_in[5];
    const float* H3b  = (const float*)d_in[6];
    const float* outw = (const float*)d_in[7];
    const float* outb = (const float*)d_in[8];
    float* out = (float*)d_out;

    int B = in_sizes[0] / 256;

    static bool attr_set = false;
    if (!attr_set) {
        cudaFuncSetAttribute(conv2fc_kernel,
                             cudaFuncAttributeMaxDynamicSharedMemorySize,
                             SM_BYTES);
        attr_set = true;
    }

    dim3 tgrid(B / 32, 8);
    transpose_kernel<<<tgrid, 256>>>(x, B);

    int nblk1 = B / 32;
    int g1 = (nblk1 + (K1_THREADS / 32) - 1) / (K1_THREADS / 32);
    conv1_kernel<<<g1, K1_THREADS>>>(H1w, H1b, B);

    int nblk2 = B / 64;
    int g2 = (nblk2 + (K2_THREADS / 32) - 1) / (K2_THREADS / 32);
    conv2fc_kernel<<<g2, K2_THREADS, SM_BYTES>>>(H2w, H2b, H3w, H3b,
                                                 outw, outb, out, B);
}